// round 8
// baseline (speedup 1.0000x reference)
#include <cuda_runtime.h>

// ---------------- dims ----------------
#define BATCH   8
#define IMG     224
#define PATCH   16
#define GRIDW   14
#define NPATCH  196
#define PD      256
#define DIM     128
#define DFF     256
#define NCLS    1000
#define MROWS   (BATCH*NPATCH)   // 1568
#define NEG_INF (-3.0e38f)

typedef unsigned long long u64;

// ---------------- packed f32x2 helpers ----------------
__device__ __forceinline__ u64 pk2(float lo, float hi) {
    u64 r;
    asm("mov.b64 %0,{%1,%2};" : "=l"(r) : "r"(__float_as_uint(lo)), "r"(__float_as_uint(hi)));
    return r;
}
__device__ __forceinline__ u64 addx2(u64 a, u64 b) {
    u64 r;
    asm("add.rn.f32x2 %0,%1,%2;" : "=l"(r) : "l"(a), "l"(b));
    return r;
}
__device__ __forceinline__ void upk2(u64 v, float& a, float& b) {
    unsigned x, y;
    asm("mov.b64 {%0,%1},%2;" : "=r"(x), "=r"(y) : "l"(v));
    a = __uint_as_float(x); b = __uint_as_float(y);
}

// ---------------- persistent scratch ----------------
__device__ float g_h   [MROWS*DIM];
__device__ float g_xn  [MROWS*DIM];
__device__ float g_q   [MROWS*DIM];
__device__ float g_kt4 [BATCH*DIM*NPATCH];
__device__ float g_v4  [BATCH*NPATCH*DIM];
__device__ float g_poolp[BATCH*7*DIM];

// blocked weights: Wt4[((j>>2)*I + i)*4 + (j&3)] = W[i*J + j]
__device__ float g_wte4[PD*DIM];
__device__ float g_wtq4[2*DIM*DIM];
__device__ float g_wtk4[2*DIM*DIM];
__device__ float g_wtv4[2*DIM*DIM];
__device__ float g_wt14[2*DFF*DIM];
__device__ float g_wt24[2*DIM*DFF];
__device__ float g_wth4[NCLS*DIM];

// ---------------- prep: transpose+block ALL weights in one launch ----------------
struct TJ { const float* src; float* dst; int I, J, base; };
struct TJobs { TJ j[12]; };

__global__ void __launch_bounds__(256) prep_k(TJobs jobs)
{
    __shared__ float tbuf[32][33];
    int b = blockIdx.x;
    int k = 0;
#pragma unroll
    for (int t = 1; t < 12; t++) if (jobs.j[t].base <= b) k = t;
    const TJ job = jobs.j[k];
    int t = b - job.base;
    int txt = (job.J + 31) / 32;
    int j0 = (t % txt) * 32, i0 = (t / txt) * 32;
    int tx = threadIdx.x & 31, ty = threadIdx.x >> 5;
    for (int yy = ty; yy < 32; yy += 8) {
        int i = i0 + yy, j = j0 + tx;
        tbuf[yy][tx] = (i < job.I && j < job.J) ? job.src[(long)i * job.J + j] : 0.f;
    }
    __syncthreads();
    for (int yy = ty; yy < 32; yy += 8) {
        int j = j0 + yy, i = i0 + tx;
        if (j < job.J && i < job.I)
            job.dst[((long)(j >> 2) * job.I + i) * 4 + (j & 3)] = tbuf[tx][yy];
    }
}

// ---------------- tropical GEMM core, TM=2, j-packed ----------------
// out[r] = max_j ( A[m0+r, j] + W[ic, j] );  As row-major [2][J]; W blocked float4 over j.
template<int NT, int J, bool PSTAGE>
__device__ __forceinline__ void trop_core2(
    const float* __restrict__ Ab, const float4* __restrict__ W4,
    float* As, int I, int m0, int ic, float out[2])
{
    const int tid = threadIdx.x;
    if (PSTAGE) {
        for (int idx = tid; idx < 2 * J; idx += NT) {
            int r = idx / J, j = idx - r * J;
            int m = m0 + r;
            int bb = m / NPATCH, n = m - bb * NPATCH;
            int gy = n / GRIDW, gx = n - gy * GRIDW;
            As[r * J + j] = Ab[((long)bb * IMG + gy * PATCH + (j >> 4)) * IMG + gx * PATCH + (j & 15)];
        }
    } else {
        const int NV = 2 * J / 4;
        for (int idx = tid; idx < NV; idx += NT) {
            int r = (idx >= J / 4) ? 1 : 0;
            int jv = idx - r * (J / 4);
            ((float4*)As)[idx] = ((const float4*)(Ab + (long)(m0 + r) * J))[jv];
        }
    }
    __syncthreads();
    float a0 = NEG_INF, a1 = NEG_INF, a2 = NEG_INF, a3 = NEG_INF;
    float b0 = NEG_INF, b1 = NEG_INF, b2 = NEG_INF, b3 = NEG_INF;
#pragma unroll 8
    for (int j = 0; j < J; j += 4) {
        float4 w = W4[(j >> 2) * I + ic];
        u64 w01 = pk2(w.x, w.y), w23 = pk2(w.z, w.w);
        ulonglong2 r0 = *(const ulonglong2*)(As + j);
        ulonglong2 r1 = *(const ulonglong2*)(As + J + j);
        u64 t0 = addx2(r0.x, w01), t1 = addx2(r0.y, w23);
        u64 t2 = addx2(r1.x, w01), t3 = addx2(r1.y, w23);
        float x, y;
        upk2(t0, x, y); a0 = fmaxf(a0, x); a1 = fmaxf(a1, y);
        upk2(t1, x, y); a2 = fmaxf(a2, x); a3 = fmaxf(a3, y);
        upk2(t2, x, y); b0 = fmaxf(b0, x); b1 = fmaxf(b1, y);
        upk2(t3, x, y); b2 = fmaxf(b2, x); b3 = fmaxf(b3, y);
    }
    out[0] = fmaxf(fmaxf(a0, a1), fmaxf(a2, a3));
    out[1] = fmaxf(fmaxf(b0, b1), fmaxf(b2, b3));
}

// block-wide max over threads for 2 row values (valid=false excludes thread's values)
template<int NT>
__device__ __forceinline__ void blk_rowmax2(float* red, float v0, float v1, float rm[2], bool valid)
{
    const int NW = NT / 32;
    int lane = threadIdx.x & 31, wid = threadIdx.x >> 5;
    float x0 = valid ? v0 : NEG_INF, x1 = valid ? v1 : NEG_INF;
#pragma unroll
    for (int o = 16; o > 0; o >>= 1) {
        x0 = fmaxf(x0, __shfl_xor_sync(0xffffffffu, x0, o));
        x1 = fmaxf(x1, __shfl_xor_sync(0xffffffffu, x1, o));
    }
    __syncthreads();             // protect red reuse
    if (lane == 0) { red[wid] = x0; red[NW + wid] = x1; }
    __syncthreads();
    float m0 = red[0], m1 = red[NW];
#pragma unroll
    for (int w = 1; w < NW; w++) { m0 = fmaxf(m0, red[w]); m1 = fmaxf(m1, red[NW + w]); }
    rm[0] = m0; rm[1] = m1;
}

// ---------------- fused kernels ----------------

// embed: patchify -> trop_mm -> +pos -> pnorm ; writes h, xn
__global__ void __launch_bounds__(128) embed_k(
    const float* __restrict__ x, const float* __restrict__ wte4, const float* __restrict__ pos,
    float* __restrict__ h, float* __restrict__ xn)
{
    __shared__ __align__(16) float As[2 * PD];
    __shared__ float red[2 * 4];
    int m0 = blockIdx.x * 2, i = threadIdx.x;
    float acc[2];
    trop_core2<128, PD, true>(x, (const float4*)wte4, As, DIM, m0, i, acc);
#pragma unroll
    for (int r = 0; r < 2; r++) {
        int m = m0 + r, n = m - (m / NPATCH) * NPATCH;
        acc[r] += pos[n * DIM + i];
    }
    float rm[2];
    blk_rowmax2<128>(red, acc[0], acc[1], rm, true);
#pragma unroll
    for (int r = 0; r < 2; r++) {
        long m = m0 + r;
        h[m * DIM + i] = acc[r];
        xn[m * DIM + i] = acc[r] - rm[r];
    }
}

// q/k/v; blockIdx.y selects weight/destination.
__global__ void __launch_bounds__(128) qkv_k(
    const float* __restrict__ xn, const float* __restrict__ wq4, const float* __restrict__ wk4,
    const float* __restrict__ wv4, float* __restrict__ q, float* __restrict__ kt4, float* __restrict__ v4)
{
    __shared__ __align__(16) float As[2 * DIM];
    int m0 = blockIdx.x * 2, i = threadIdx.x, y = blockIdx.y;
    const float* W4 = (y == 0) ? wq4 : (y == 1) ? wk4 : wv4;
    float acc[2];
    trop_core2<128, DIM, false>(xn, (const float4*)W4, As, DIM, m0, i, acc);
#pragma unroll
    for (int r = 0; r < 2; r++) {
        int m = m0 + r;
        if (y == 0) {
            q[(long)m * DIM + i] = acc[r];
        } else {
            int b = m / NPATCH, n = m - b * NPATCH;
            if (y == 1) kt4[(long)b * DIM * NPATCH + ((i >> 2) * NPATCH + n) * 4 + (i & 3)] = acc[r];
            else        v4 [(long)b * NPATCH * DIM + ((n >> 2) * DIM + i) * 4 + (n & 3)] = acc[r];
        }
    }
}

// fused scores+attn: block = 2 score rows of one batch, 256 threads
__global__ void __launch_bounds__(256) sa_k(
    const float* __restrict__ q, const float* __restrict__ kt4, const float* __restrict__ v4,
    float* __restrict__ h, float* __restrict__ xn)
{
    __shared__ __align__(16) float qs[2 * DIM];
    __shared__ __align__(16) float scs[2 * NPATCH];
    __shared__ __align__(16) float part[2 * DIM];
    __shared__ float red[2 * 8];
    const int b = blockIdx.y, m0 = blockIdx.x * 2;
    const int tid = threadIdx.x;

    // ---- phase 1: scores for 2 rows ----
    const bool valid = (tid < NPATCH);
    const int ic = min(tid, NPATCH - 1);
    float acc[2];
    trop_core2<256, DIM, false>(q + (long)b * NPATCH * DIM,
                                (const float4*)(kt4 + (long)b * DIM * NPATCH),
                                qs, NPATCH, m0, ic, acc);
    float rm[2];
    blk_rowmax2<256>(red, acc[0], acc[1], rm, valid);
    if (valid) { scs[tid] = acc[0]; scs[NPATCH + tid] = acc[1]; }
    __syncthreads();

    // ---- phase 2: out[m,d] = max_j(sc+v), j split across halves ----
    const int d = tid & 127, hh = tid >> 7;
    const int j0 = hh ? 96 : 0, j1 = hh ? 196 : 96;
    const float4* V4 = (const float4*)(v4 + (long)b * NPATCH * DIM);
    float p0a = NEG_INF, p0b = NEG_INF, p1a = NEG_INF, p1b = NEG_INF;
#pragma unroll 4
    for (int j = j0; j < j1; j += 4) {
        float4 v = V4[(j >> 2) * DIM + d];
        u64 v01 = pk2(v.x, v.y), v23 = pk2(v.z, v.w);
        ulonglong2 s0 = *(const ulonglong2*)(scs + j);
        ulonglong2 s1 = *(const ulonglong2*)(scs + NPATCH + j);
        u64 t0 = addx2(s0.x, v01), t1 = addx2(s0.y, v23);
        u64 t2 = addx2(s1.x, v01), t3 = addx2(s1.y, v23);
        float x, y;
        upk2(t0, x, y); p0a = fmaxf(p0a, x); p0b = fmaxf(p0b, y);
        upk2(t1, x, y); p0a = fmaxf(p0a, x); p0b = fmaxf(p0b, y);
        upk2(t2, x, y); p1a = fmaxf(p1a, x); p1b = fmaxf(p1b, y);
        upk2(t3, x, y); p1a = fmaxf(p1a, x); p1b = fmaxf(p1b, y);
    }
    float p0 = fmaxf(p0a, p0b), p1 = fmaxf(p1a, p1b);
    if (hh) { part[d] = p0; part[DIM + d] = p1; }
    __syncthreads();
    float av0 = NEG_INF, av1 = NEG_INF;
    if (!hh) {
        av0 = fmaxf(p0, part[d]) - rm[0];
        av1 = fmaxf(p1, part[DIM + d]) - rm[1];
    }
    float am[2];
    blk_rowmax2<256>(red, av0, av1, am, !hh);
    const long row0 = (long)b * NPATCH + m0;
    float hv0 = NEG_INF, hv1 = NEG_INF;
    if (!hh) {
        hv0 = fmaxf(h[row0 * DIM + d], av0 - am[0]);
        hv1 = fmaxf(h[(row0 + 1) * DIM + d], av1 - am[1]);
    }
    float hm[2];
    blk_rowmax2<256>(red, hv0, hv1, hm, !hh);
    if (!hh) {
        h[row0 * DIM + d] = hv0;        xn[row0 * DIM + d] = hv0 - hm[0];
        h[(row0 + 1) * DIM + d] = hv1;  xn[(row0 + 1) * DIM + d] = hv1 - hm[1];
    }
}

// fused ff1+ff2: block = 2 rows, 256 threads
// phase1: ffh[2][256] = max(trop_mm(xn, f1W), tau) in smem
// phase2: ff = trop_mm(ffh, f2W); pnorm; h=max(h,.); xn=pnorm(h)
__global__ void __launch_bounds__(256) ff_k(
    const float* __restrict__ xn, const float* __restrict__ w14, const float* __restrict__ w24,
    const float* __restrict__ tau, float* __restrict__ h)
{
    __shared__ __align__(16) float xs[2 * DIM];
    __shared__ __align__(16) float fs[2 * DFF];
    __shared__ __align__(16) float part[2 * DIM];
    __shared__ float red[2 * 8];
    const int m0 = blockIdx.x * 2, tid = threadIdx.x;

    // ---- phase 1: ff1 (thread per DFF column) ----
    float acc[2];
    trop_core2<256, DIM, false>(xn, (const float4*)w14, xs, DFF, m0, tid, acc);
    float tv = tau[0];
    fs[tid] = fmaxf(acc[0], tv);
    fs[DFF + tid] = fmaxf(acc[1], tv);
    __syncthreads();

    // ---- phase 2: ff2, j split across halves ----
    const int d = tid & 127, hh = tid >> 7;
    const int j0 = hh * 128, j1 = j0 + 128;
    const float4* W2 = (const float4*)w24;
    float p0a = NEG_INF, p0b = NEG_INF, p1a = NEG_INF, p1b = NEG_INF;
#pragma unroll 8
    for (int j = j0; j < j1; j += 4) {
        float4 w = W2[(j >> 2) * DIM + d];
        u64 w01 = pk2(w.x, w.y), w23 = pk2(w.z, w.w);
        ulonglong2 s0 = *(const ulonglong2*)(fs + j);
        ulonglong2 s1 = *(const ulonglong2*)(fs + DFF + j);
        u64 t0 = addx2(s0.x, w01), t1 = addx2(s0.y, w23);
        u64 t2 = addx2(s1.x, w01), t3 = addx2(s1.y, w23);
        float x, y;
        upk2(t0, x, y); p0a = fmaxf(p0a, x); p0b = fmaxf(p0b, y);
        upk2(t1, x, y); p0a = fmaxf(p0a, x); p0b = fmaxf(p0b, y);
        upk2(t2, x, y); p1a = fmaxf(p1a, x); p1b = fmaxf(p1b, y);
        upk2(t3, x, y); p1a = fmaxf(p1a, x); p1b = fmaxf(p1b, y);
    }
    float p0 = fmaxf(p0a, p0b), p1 = fmaxf(p1a, p1b);
    if (hh) { part[d] = p0; part[DIM + d] = p1; }
    __syncthreads();
    float f0 = NEG_INF, f1 = NEG_INF;
    if (!hh) {
        f0 = fmaxf(p0, part[d]);
        f1 = fmaxf(p1, part[DIM + d]);
    }
    float am[2];
    blk_rowmax2<256>(red, f0, f1, am, !hh);
    float hv0 = NEG_INF, hv1 = NEG_INF;
    const long row0 = m0;
    if (!hh) {
        hv0 = fmaxf(h[row0 * DIM + d], f0 - am[0]);
        hv1 = fmaxf(h[(row0 + 1) * DIM + d], f1 - am[1]);
    }
    float hm[2];
    blk_rowmax2<256>(red, hv0, hv1, hm, !hh);
    if (!hh) {
        h[row0 * DIM + d] = hv0;
        h[(row0 + 1) * DIM + d] = hv1;
        float* xno = (float*)xn;   // xn buffer is both input (read in phase1) and output
        xno[row0 * DIM + d] = hv0 - hm[0];
        xno[(row0 + 1) * DIM + d] = hv1 - hm[1];
    }
}

// partial pool over 28-patch chunks
__global__ void __launch_bounds__(128) pool1_k(const float* __restrict__ H, float* __restrict__ Pp)
{
    int b = blockIdx.x, c = blockIdx.y, tid = threadIdx.x;
    const float* hp = H + ((long)b * NPATCH + c * 28) * DIM + tid;
    float m = NEG_INF;
#pragma unroll 4
    for (int n = 0; n < 28; n++) m = fmaxf(m, hp[(long)n * DIM]);
    Pp[(b * 7 + c) * DIM + tid] = m;
}

__global__ void __launch_bounds__(128) head_k(
    const float* __restrict__ Pp, const float* __restrict__ w4,
    const float* __restrict__ ls, float* __restrict__ O)
{
    __shared__ float sp[DIM];
    int b = blockIdx.y, tid = threadIdx.x;
    float m = NEG_INF;
#pragma unroll
    for (int c = 0; c < 7; c++) m = fmaxf(m, Pp[(b * 7 + c) * DIM + tid]);
    sp[tid] = m;
    __syncthreads();
    int c = blockIdx.x * 128 + tid;
    if (c < NCLS) {
        const float4* W = (const float4*)w4;
        float acc = NEG_INF;
#pragma unroll 4
        for (int j = 0; j < DIM; j += 4) {
            float4 w = W[(j >> 2) * NCLS + c];
            acc = fmaxf(acc, sp[j + 0] + w.x);
            acc = fmaxf(acc, sp[j + 1] + w.y);
            acc = fmaxf(acc, sp[j + 2] + w.z);
            acc = fmaxf(acc, sp[j + 3] + w.w);
        }
        O[(long)b * NCLS + c] = acc * ls[0];
    }
}

// ---------------- launch ----------------
extern "C" void kernel_launch(void* const* d_in, const int* in_sizes, int n_in,
                              void* d_out, int out_size)
{
    (void)in_sizes; (void)n_in; (void)out_size;
    const float* x      = (const float*)d_in[0];
    const float* embedW = (const float*)d_in[1];
    const float* pos    = (const float*)d_in[2];
    const float* W[2][5];
    const float* tau[2];
    for (int l = 0; l < 2; l++) {
        int base = 3 + l * 6;
        for (int k = 0; k < 5; k++) W[l][k] = (const float*)d_in[base + k];
        tau[l] = (const float*)d_in[base + 5];
    }
    const float* headW  = (const float*)d_in[15];
    const float* lscale = (const float*)d_in[16];
    float* out = (float*)d_out;

    float *h, *xn, *q, *kt4, *v4, *poolp;
    float *wte4, *wtq4, *wtk4, *wtv4, *wt14, *wt24, *wth4;
    cudaGetSymbolAddress((void**)&h,    g_h);
    cudaGetSymbolAddress((void**)&xn,   g_xn);
    cudaGetSymbolAddress((void**)&q,    g_q);
    cudaGetSymbolAddress((void**)&kt4,  g_kt4);
    cudaGetSymbolAddress((void**)&v4,   g_v4);
    cudaGetSymbolAddress((void**)&poolp,g_poolp);
    cudaGetSymbolAddress((void**)&wte4, g_wte4);
    cudaGetSymbolAddress((void**)&wtq4, g_wtq4);
    cudaGetSymbolAddress((void**)&wtk4, g_wtk4);
    cudaGetSymbolAddress((void**)&wtv4, g_wtv4);
    cudaGetSymbolAddress((void**)&wt14, g_wt14);
    cudaGetSymbolAddress((void**)&wt24, g_wt24);
    cudaGetSymbolAddress((void**)&wth4, g_wth4);

    TJobs jobs;
    int base = 0, nj = 0;
    auto addJob = [&](const float* s, float* d, int I, int J) {
        jobs.j[nj].src = s; jobs.j[nj].dst = d; jobs.j[nj].I = I; jobs.j[nj].J = J;
        jobs.j[nj].base = base;
        base += ((J + 31) / 32) * ((I + 31) / 32);
        nj++;
    };
    addJob(embedW, wte4, DIM, PD);
    for (int l = 0; l < 2; l++) {
        addJob(W[l][0], wtq4 + l * DIM * DIM, DIM, DIM);
        addJob(W[l][1], wtk4 + l * DIM * DIM, DIM, DIM);
        addJob(W[l][2], wtv4 + l * DIM * DIM, DIM, DIM);
        addJob(W[l][3], wt14 + l * DFF * DIM, DFF, DIM);
        addJob(W[l][4], wt24 + l * DIM * DFF, DIM, DFF);
    }
    addJob(headW, wth4, NCLS, DIM);

    prep_k<<<base, 256>>>(jobs);
    embed_k<<<784, 128>>>(x, wte4, pos, h, xn);

    for (int l = 0; l < 2; l++) {
        qkv_k<<<dim3(784, 3), 128>>>(xn, wtq4 + l * DIM * DIM, wtk4 + l * DIM * DIM,
                                     wtv4 + l * DIM * DIM, q, kt4, v4);
        sa_k<<<dim3(98, 8), 256>>>(q, kt4, v4, h, xn);
        ff_k<<<784, 256>>>(xn, wt14 + l * DFF * DIM, wt24 + l * DIM * DFF, tau[l], h);
    }

    pool1_k<<<dim3(8, 7), 128>>>(h, poolp);
    head_k<<<dim3(8, 8), 128>>>(poolp, wth4, lscale, out);
}

// round 10
// speedup vs baseline: 1.1931x; 1.1931x over previous
#include <cuda_runtime.h>

// ---------------- dims ----------------
#define BATCH   8
#define IMG     224
#define PATCH   16
#define GRIDW   14
#define NPATCH  196
#define PD      256
#define DIM     128
#define DFF     256
#define NCLS    1000
#define MROWS   (BATCH*NPATCH)   // 1568
#define NEG_INF (-3.0e38f)

typedef unsigned long long u64;

// ---------------- packed f32x2 helpers ----------------
__device__ __forceinline__ u64 pk2(float lo, float hi) {
    u64 r;
    asm("mov.b64 %0,{%1,%2};" : "=l"(r) : "r"(__float_as_uint(lo)), "r"(__float_as_uint(hi)));
    return r;
}
__device__ __forceinline__ u64 addx2(u64 a, u64 b) {
    u64 r;
    asm("add.rn.f32x2 %0,%1,%2;" : "=l"(r) : "l"(a), "l"(b));
    return r;
}
__device__ __forceinline__ void upk2(u64 v, float& a, float& b) {
    unsigned x, y;
    asm("mov.b64 {%0,%1},%2;" : "=r"(x), "=r"(y) : "l"(v));
    a = __uint_as_float(x); b = __uint_as_float(y);
}

// ---------------- persistent scratch ----------------
__device__ float g_h   [MROWS*DIM];
__device__ float g_xn  [MROWS*DIM];
__device__ float g_q   [MROWS*DIM];
__device__ float g_kt4 [BATCH*DIM*NPATCH];
__device__ float g_v4  [BATCH*NPATCH*DIM];
__device__ float g_poolp[BATCH*7*DIM];

// blocked weights: Wt4[((j>>2)*I + i)*4 + (j&3)] = W[i*J + j]
__device__ float g_wte4[PD*DIM];
__device__ float g_wtq4[2*DIM*DIM];
__device__ float g_wtk4[2*DIM*DIM];
__device__ float g_wtv4[2*DIM*DIM];
__device__ float g_wt14[2*DFF*DIM];
__device__ float g_wt24[2*DIM*DFF];
__device__ float g_wth4[NCLS*DIM];

// ---------------- prep: transpose+block ALL weights in one launch ----------------
struct TJ { const float* src; float* dst; int I, J, base; };
struct TJobs { TJ j[12]; };

__global__ void __launch_bounds__(256) prep_k(TJobs jobs)
{
    __shared__ float tbuf[32][33];
    int b = blockIdx.x;
    int k = 0;
#pragma unroll
    for (int t = 1; t < 12; t++) if (jobs.j[t].base <= b) k = t;
    const TJ job = jobs.j[k];
    int t = b - job.base;
    int txt = (job.J + 31) / 32;
    int j0 = (t % txt) * 32, i0 = (t / txt) * 32;
    int tx = threadIdx.x & 31, ty = threadIdx.x >> 5;
    for (int yy = ty; yy < 32; yy += 8) {
        int i = i0 + yy, j = j0 + tx;
        tbuf[yy][tx] = (i < job.I && j < job.J) ? job.src[(long)i * job.J + j] : 0.f;
    }
    __syncthreads();
    for (int yy = ty; yy < 32; yy += 8) {
        int j = j0 + yy, i = i0 + tx;
        if (j < job.J && i < job.I)
            job.dst[((long)(j >> 2) * job.I + i) * 4 + (j & 3)] = tbuf[tx][yy];
    }
}

// ---------------- tropical GEMM core: TM=4, row-major A tile, j-packed weights ----
// out[r] = max_j ( A[m0+r, j] + W[ic, j] )
template<int NT, int J, bool PSTAGE>
__device__ __forceinline__ void core4(
    const float* __restrict__ Ab, const float4* __restrict__ W4,
    float* As, int I, int m0, int ic, float out[4])
{
    const int tid = threadIdx.x;
    if (PSTAGE) {
        for (int idx = tid; idx < 4 * J; idx += NT) {
            int r = idx / J, j = idx - r * J;
            int m = m0 + r;
            int bb = m / NPATCH, n = m - bb * NPATCH;
            int gy = n / GRIDW, gx = n - gy * GRIDW;
            As[r * J + j] = Ab[((long)bb * IMG + gy * PATCH + (j >> 4)) * IMG + gx * PATCH + (j & 15)];
        }
    } else {
        for (int idx = tid; idx < J; idx += NT) {   // J float4s = 4 rows * J/4
            int r = idx / (J / 4), jv = idx - r * (J / 4);
            ((float4*)As)[idx] = ((const float4*)(Ab + (long)(m0 + r) * J))[jv];
        }
    }
    __syncthreads();
    float c0[4], c1[4], c2[4], c3[4];
#pragma unroll
    for (int r = 0; r < 4; r++) { c0[r] = NEG_INF; c1[r] = NEG_INF; c2[r] = NEG_INF; c3[r] = NEG_INF; }
#pragma unroll 8
    for (int j = 0; j < J; j += 4) {
        float4 w = W4[(j >> 2) * I + ic];
        u64 w01 = pk2(w.x, w.y), w23 = pk2(w.z, w.w);
#pragma unroll
        for (int r = 0; r < 4; r++) {
            ulonglong2 a = *(const ulonglong2*)(As + r * J + j);
            u64 t0 = addx2(a.x, w01), t1 = addx2(a.y, w23);
            float x, y;
            upk2(t0, x, y); c0[r] = fmaxf(c0[r], x); c1[r] = fmaxf(c1[r], y);
            upk2(t1, x, y); c2[r] = fmaxf(c2[r], x); c3[r] = fmaxf(c3[r], y);
        }
    }
#pragma unroll
    for (int r = 0; r < 4; r++)
        out[r] = fmaxf(fmaxf(c0[r], c1[r]), fmaxf(c2[r], c3[r]));
}

// block-wide max of K values per thread (valid=false excludes this thread's values)
template<int NT, int K>
__device__ __forceinline__ void rowmaxK(float* red, const float* v, float* out, bool valid)
{
    const int NW = NT / 32;
    int lane = threadIdx.x & 31, wid = threadIdx.x >> 5;
    float x[K];
#pragma unroll
    for (int k = 0; k < K; k++) {
        x[k] = valid ? v[k] : NEG_INF;
#pragma unroll
        for (int o = 16; o > 0; o >>= 1) x[k] = fmaxf(x[k], __shfl_xor_sync(0xffffffffu, x[k], o));
    }
    __syncthreads();
    if (lane == 0) {
#pragma unroll
        for (int k = 0; k < K; k++) red[k * NW + wid] = x[k];
    }
    __syncthreads();
#pragma unroll
    for (int k = 0; k < K; k++) {
        float m = red[k * NW];
#pragma unroll
        for (int w = 1; w < NW; w++) m = fmaxf(m, red[k * NW + w]);
        out[k] = m;
    }
}

// ---------------- fused kernels ----------------

// embed: patchify -> trop_mm -> +pos -> pnorm ; writes h, xn
__global__ void __launch_bounds__(128) embed_k(
    const float* __restrict__ x, const float* __restrict__ wte4, const float* __restrict__ pos,
    float* __restrict__ h, float* __restrict__ xn)
{
    __shared__ __align__(16) float As[4 * PD];
    __shared__ float red[4 * 4];
    const int m0 = blockIdx.x * 4, i = threadIdx.x;
    float acc[4];
    core4<128, PD, true>(x, (const float4*)wte4, As, DIM, m0, i, acc);
    const int n0 = m0 - (m0 / NPATCH) * NPATCH;
#pragma unroll
    for (int r = 0; r < 4; r++) acc[r] += pos[(n0 + r) * DIM + i];
    float rm[4];
    rowmaxK<128, 4>(red, acc, rm, true);
#pragma unroll
    for (int r = 0; r < 4; r++) {
        long m = m0 + r;
        h[m * DIM + i] = acc[r];
        xn[m * DIM + i] = acc[r] - rm[r];
    }
}

// q/k/v fused: 384 threads, A tile staged once; y = tid>>7 selects q/k/v
__global__ void __launch_bounds__(384) qkv_k(
    const float* __restrict__ xn, const float* __restrict__ wq4, const float* __restrict__ wk4,
    const float* __restrict__ wv4, float* __restrict__ q, float* __restrict__ kt4, float* __restrict__ v4)
{
    __shared__ __align__(16) float As[4 * DIM];
    const int m0 = blockIdx.x * 4, tid = threadIdx.x;
    const int y = tid >> 7, c = tid & 127;
    const float* W = (y == 0) ? wq4 : (y == 1) ? wk4 : wv4;
    float acc[4];
    core4<384, DIM, false>(xn, (const float4*)W, As, DIM, m0, c, acc);
    const int b = m0 / NPATCH, n0 = m0 - b * NPATCH;
#pragma unroll
    for (int r = 0; r < 4; r++) {
        int m = m0 + r, n = n0 + r;
        if (y == 0)      q[(long)m * DIM + c] = acc[r];
        else if (y == 1) kt4[(long)b * DIM * NPATCH + ((c >> 2) * NPATCH + n) * 4 + (c & 3)] = acc[r];
        else             v4 [(long)b * NPATCH * DIM + ((n >> 2) * DIM + c) * 4 + (n & 3)] = acc[r];
    }
}

// fused scores+attn for 4 rows of one batch, 256 threads.
// NOTE: the per-row score max cancels exactly through the output pnorm, so no
// phase-1 reduction is needed. Epilogue uses the merged reduction:
//   am = rowmax(raw), hm = max(rowmax(h_old), 0).
__global__ void __launch_bounds__(256) sa_k(
    const float* __restrict__ q, const float* __restrict__ kt4, const float* __restrict__ v4,
    float* __restrict__ h, float* __restrict__ xn)
{
    __shared__ __align__(16) float qs[4 * DIM];
    __shared__ __align__(16) float scs[NPATCH * 4];
    __shared__ __align__(16) float part[4 * DIM];
    __shared__ float red[8 * 8];
    const int b = blockIdx.y, m0 = blockIdx.x * 4;
    const int tid = threadIdx.x;

    // ---- phase 1: raw scores for 4 rows (thread = key column n) ----
    {
        const int n = tid;
        const int ic = min(n, NPATCH - 1);
        float acc[4];
        core4<256, DIM, false>(q + (long)b * NPATCH * DIM,
                               (const float4*)(kt4 + (long)b * DIM * NPATCH),
                               qs, NPATCH, m0, ic, acc);
        if (n < NPATCH) *(float4*)(scs + n * 4) = make_float4(acc[0], acc[1], acc[2], acc[3]);
    }
    __syncthreads();

    // ---- phase 2: raw out[m,d] = max_n(sc[n,m] + v[n,d]); n-range split in halves ----
    const int d = tid & 127, hh = tid >> 7;
    const int n0 = hh ? 96 : 0, n1 = hh ? 196 : 96;
    const float4* V4 = (const float4*)(v4 + (long)b * NPATCH * DIM);
    float pa[4], pb[4];
#pragma unroll
    for (int r = 0; r < 4; r++) { pa[r] = NEG_INF; pb[r] = NEG_INF; }
#pragma unroll 4
    for (int n = n0; n < n1; n += 4) {
        float4 vv = V4[(n >> 2) * DIM + d];
        float vs[4] = { vv.x, vv.y, vv.z, vv.w };
#pragma unroll
        for (int nn = 0; nn < 4; nn++) {
            u64 vd = pk2(vs[nn], vs[nn]);
            ulonglong2 s = *(const ulonglong2*)(scs + (n + nn) * 4);
            u64 t0 = addx2(s.x, vd), t1 = addx2(s.y, vd);
            float x, y;
            float* p = (nn & 1) ? pb : pa;
            upk2(t0, x, y); p[0] = fmaxf(p[0], x); p[1] = fmaxf(p[1], y);
            upk2(t1, x, y); p[2] = fmaxf(p[2], x); p[3] = fmaxf(p[3], y);
        }
    }
    float raw[4];
#pragma unroll
    for (int r = 0; r < 4; r++) raw[r] = fmaxf(pa[r], pb[r]);
    if (hh) *(float4*)(part + d * 4) = make_float4(raw[0], raw[1], raw[2], raw[3]);
    __syncthreads();

    // ---- epilogue: combine halves, joint reduction, residual + pnorm ----
    const long row0 = ((long)b * NPATCH + m0) * DIM;
    float v8[8];
#pragma unroll
    for (int k = 0; k < 8; k++) v8[k] = NEG_INF;
    const bool lo = (hh == 0);
    if (lo) {
        float4 o = *(const float4*)(part + d * 4);
        v8[0] = fmaxf(raw[0], o.x); v8[1] = fmaxf(raw[1], o.y);
        v8[2] = fmaxf(raw[2], o.z); v8[3] = fmaxf(raw[3], o.w);
#pragma unroll
        for (int r = 0; r < 4; r++) v8[4 + r] = h[row0 + r * DIM + d];
    }
    float o8[8];
    rowmaxK<256, 8>(red, v8, o8, lo);
    if (lo) {
#pragma unroll
        for (int r = 0; r < 4; r++) {
            float hv = fmaxf(v8[4 + r], v8[r] - o8[r]);     // max(h_old, a - rowmax(a))
            float hm = fmaxf(o8[4 + r], 0.f);               // rowmax of new h
            h[row0 + r * DIM + d] = hv;
            xn[row0 + r * DIM + d] = hv - hm;
        }
    }
}

// fused ff1+ff2 for 4 rows, 256 threads; same merged-reduction epilogue.
__global__ void __launch_bounds__(256) ff_k(
    const float* __restrict__ xn, const float* __restrict__ w14, const float* __restrict__ w24,
    const float* __restrict__ tau, float* __restrict__ h)
{
    __shared__ __align__(16) float xs[4 * DIM];
    __shared__ __align__(16) float fs[DFF * 4];
    __shared__ __align__(16) float part[4 * DIM];
    __shared__ float red[8 * 8];
    const int m0 = blockIdx.x * 4, tid = threadIdx.x;

    // ---- phase 1: ffh (thread = DFF column) ----
    {
        float acc[4];
        core4<256, DIM, false>(xn, (const float4*)w14, xs, DFF, m0, tid, acc);
        float tv = tau[0];
        *(float4*)(fs + tid * 4) = make_float4(fmaxf(acc[0], tv), fmaxf(acc[1], tv),
                                               fmaxf(acc[2], tv), fmaxf(acc[3], tv));
    }
    __syncthreads();

    // ---- phase 2: raw ff[m,d] = max_j(fs[j,m] + w2[d,j]); j-range split in halves ----
    const int d = tid & 127, hh = tid >> 7;
    const int j0 = hh * 128, j1 = j0 + 128;
    const float4* W2 = (const float4*)w24;
    float pa[4], pb[4];
#pragma unroll
    for (int r = 0; r < 4; r++) { pa[r] = NEG_INF; pb[r] = NEG_INF; }
#pragma unroll 4
    for (int j = j0; j < j1; j += 4) {
        float4 ww = W2[(j >> 2) * DIM + d];
        float ws[4] = { ww.x, ww.y, ww.z, ww.w };
#pragma unroll
        for (int jj = 0; jj < 4; jj++) {
            u64 wd = pk2(ws[jj], ws[jj]);
            ulonglong2 s = *(const ulonglong2*)(fs + (j + jj) * 4);
            u64 t0 = addx2(s.x, wd), t1 = addx2(s.y, wd);
            float x, y;
            float* p = (jj & 1) ? pb : pa;
            upk2(t0, x, y); p[0] = fmaxf(p[0], x); p[1] = fmaxf(p[1], y);
            upk2(t1, x, y); p[2] = fmaxf(p[2], x); p[3] = fmaxf(p[3], y);
        }
    }
    float raw[4];
#pragma unroll
    for (int r = 0; r < 4; r++) raw[r] = fmaxf(pa[r], pb[r]);
    if (hh) *(float4*)(part + d * 4) = make_float4(raw[0], raw[1], raw[2], raw[3]);
    __syncthreads();

    const long row0 = (long)m0 * DIM;
    float v8[8];
#pragma unroll
    for (int k = 0; k < 8; k++) v8[k] = NEG_INF;
    const bool lo = (hh == 0);
    if (lo) {
        float4 o = *(const float4*)(part + d * 4);
        v8[0] = fmaxf(raw[0], o.x); v8[1] = fmaxf(raw[1], o.y);
        v8[2] = fmaxf(raw[2], o.z); v8[3] = fmaxf(raw[3], o.w);
#pragma unroll
        for (int r = 0; r < 4; r++) v8[4 + r] = h[row0 + r * DIM + d];
    }
    float o8[8];
    rowmaxK<256, 8>(red, v8, o8, lo);
    if (lo) {
        float* xno = (float*)xn;   // per-block rows only: no cross-block hazard
#pragma unroll
        for (int r = 0; r < 4; r++) {
            float hv = fmaxf(v8[4 + r], v8[r] - o8[r]);
            float hm = fmaxf(o8[4 + r], 0.f);
            h[row0 + r * DIM + d] = hv;
            xno[row0 + r * DIM + d] = hv - hm;
        }
    }
}

// partial pool over 28-patch chunks
__global__ void __launch_bounds__(128) pool1_k(const float* __restrict__ H, float* __restrict__ Pp)
{
    int b = blockIdx.x, c = blockIdx.y, tid = threadIdx.x;
    const float* hp = H + ((long)b * NPATCH + c * 28) * DIM + tid;
    float m = NEG_INF;
#pragma unroll 4
    for (int n = 0; n < 28; n++) m = fmaxf(m, hp[(long)n * DIM]);
    Pp[(b * 7 + c) * DIM + tid] = m;
}

__global__ void __launch_bounds__(128) head_k(
    const float* __restrict__ Pp, const float* __restrict__ w4,
    const float* __restrict__ ls, float* __restrict__ O)
{
    __shared__ float sp[DIM];
    int b = blockIdx.y, tid = threadIdx.x;
    float m = NEG_INF;
#pragma unroll
    for (int c = 0; c < 7; c++) m = fmaxf(m, Pp[(b * 7 + c) * DIM + tid]);
    sp[tid] = m;
    __syncthreads();
    int c = blockIdx.x * 128 + tid;
    if (c < NCLS) {
        const float4* W = (const float4*)w4;
        float acc = NEG_INF;
#pragma unroll 4
        for (int j = 0; j < DIM; j += 4) {
            float4 w = W[(j >> 2) * NCLS + c];
            acc = fmaxf(acc, sp[j + 0] + w.x);
            acc = fmaxf(acc, sp[j + 1] + w.y);
            acc = fmaxf(acc, sp[j + 2] + w.z);
            acc = fmaxf(acc, sp[j + 3] + w.w);
        }
        O[(long)b * NCLS + c] = acc * ls[0];
    }
}

// ---------------- launch ----------------
extern "C" void kernel_launch(void* const* d_in, const int* in_sizes, int n_in,
                              void* d_out, int out_size)
{
    (void)in_sizes; (void)n_in; (void)out_size;
    const float* x      = (const float*)d_in[0];
    const float* embedW = (const float*)d_in[1];
    const float* pos    = (const float*)d_in[2];
    const float* W[2][5];
    const float* tau[2];
    for (int l = 0; l < 2; l++) {
        int base = 3 + l * 6;
        for (int k = 0; k < 5; k++) W[l][k] = (const float*)d_in[base + k];
        tau[l] = (const float*)d_in[base + 5];
    }
    const float* headW  = (const float*)d_in[15];
    const float* lscale = (const float*)d_in[16];
    float* out = (float*)d_out;

    float *h, *xn, *q, *kt4, *v4, *poolp;
    float *wte4, *wtq4, *wtk4, *wtv4, *wt14, *wt24, *wth4;
    cudaGetSymbolAddress((void**)&h,    g_h);
    cudaGetSymbolAddress((void**)&xn,   g_xn);
    cudaGetSymbolAddress((void**)&q,    g_q);
    cudaGetSymbolAddress((void**)&kt4,  g_kt4);
    cudaGetSymbolAddress((void**)&v4,   g_v4);
    cudaGetSymbolAddress((void**)&poolp,g_poolp);
    cudaGetSymbolAddress((void**)&wte4, g_wte4);
    cudaGetSymbolAddress((void**)&wtq4, g_wtq4);
    cudaGetSymbolAddress((void**)&wtk4, g_wtk4);
    cudaGetSymbolAddress((void**)&wtv4, g_wtv4);
    cudaGetSymbolAddress((void**)&wt14, g_wt14);
    cudaGetSymbolAddress((void**)&wt24, g_wt24);
    cudaGetSymbolAddress((void**)&wth4, g_wth4);

    TJobs jobs;
    int base = 0, nj = 0;
    auto addJob = [&](const float* s, float* d, int I, int J) {
        jobs.j[nj].src = s; jobs.j[nj].dst = d; jobs.j[nj].I = I; jobs.j[nj].J = J;
        jobs.j[nj].base = base;
        base += ((J + 31) / 32) * ((I + 31) / 32);
        nj++;
    };
    addJob(embedW, wte4, DIM, PD);
    for (int l = 0; l < 2; l++) {
        addJob(W[l][0], wtq4 + l * DIM * DIM, DIM, DIM);
        addJob(W[l][1], wtk4 + l * DIM * DIM, DIM, DIM);
        addJob(W[l][2], wtv4 + l * DIM * DIM, DIM, DIM);
        addJob(W[l][3], wt14 + l * DFF * DIM, DFF, DIM);
        addJob(W[l][4], wt24 + l * DIM * DFF, DIM, DFF);
    }
    addJob(headW, wth4, NCLS, DIM);

    prep_k<<<base, 256>>>(jobs);
    embed_k<<<392, 128>>>(x, wte4, pos, h, xn);

    for (int l = 0; l < 2; l++) {
        qkv_k<<<392, 384>>>(xn, wtq4 + l * DIM * DIM, wtk4 + l * DIM * DIM,
                            wtv4 + l * DIM * DIM, q, kt4, v4);
        sa_k<<<dim3(49, 8), 256>>>(q, kt4, v4, h, xn);
        ff_k<<<392, 256>>>(xn, wt14 + l * DFF * DIM, wt24 + l * DIM * DFF, tau[l], h);
    }

    pool1_k<<<dim3(8, 7), 128>>>(h, poolp);
    head_k<<<dim3(8, 8), 128>>>(poolp, wth4, lscale, out);
}

// round 11
// speedup vs baseline: 1.1935x; 1.0003x over previous
#include <cuda_runtime.h>

// ---------------- dims ----------------
#define BATCH   8
#define IMG     224
#define PATCH   16
#define GRIDW   14
#define NPATCH  196
#define PD      256
#define DIM     128
#define DFF     256
#define NCLS    1000
#define MROWS   (BATCH*NPATCH)   // 1568
#define NEG_INF (-3.0e38f)

typedef unsigned long long u64;

// ---------------- packed f32x2 helpers ----------------
__device__ __forceinline__ u64 pk2(float lo, float hi) {
    u64 r;
    asm("mov.b64 %0,{%1,%2};" : "=l"(r) : "r"(__float_as_uint(lo)), "r"(__float_as_uint(hi)));
    return r;
}
__device__ __forceinline__ u64 addx2(u64 a, u64 b) {
    u64 r;
    asm("add.rn.f32x2 %0,%1,%2;" : "=l"(r) : "l"(a), "l"(b));
    return r;
}
__device__ __forceinline__ void upk2(u64 v, float& a, float& b) {
    unsigned x, y;
    asm("mov.b64 {%0,%1},%2;" : "=r"(x), "=r"(y) : "l"(v));
    a = __uint_as_float(x); b = __uint_as_float(y);
}

// order-preserving float<->uint key for atomicMax pooling
__device__ __forceinline__ unsigned fkey(float f) {
    unsigned u = __float_as_uint(f);
    return (u & 0x80000000u) ? ~u : (u | 0x80000000u);
}
__device__ __forceinline__ float funkey(unsigned u) {
    return (u & 0x80000000u) ? __uint_as_float(u & 0x7fffffffu) : __uint_as_float(~u);
}

// ---------------- persistent scratch ----------------
__device__ float    g_h   [MROWS*DIM];
__device__ float    g_xn  [MROWS*DIM];
__device__ float    g_q   [MROWS*DIM];
__device__ float    g_kt4 [BATCH*DIM*NPATCH];
__device__ float    g_v4  [BATCH*NPATCH*DIM];
__device__ unsigned g_poolk[BATCH*DIM];

// blocked weights: Wt4[((j>>2)*I + i)*4 + (j&3)] = W[i*J + j]
__device__ float g_wte4[PD*DIM];
__device__ float g_wtq4[2*DIM*DIM];
__device__ float g_wtk4[2*DIM*DIM];
__device__ float g_wtv4[2*DIM*DIM];
__device__ float g_wt14[2*DFF*DIM];
__device__ float g_wt24[2*DIM*DFF];
__device__ float g_wth4[NCLS*DIM];

// ---------------- prep: transpose+block ALL weights; clear pool keys ----------------
struct TJ { const float* src; float* dst; int I, J, base; };
struct TJobs { TJ j[12]; };

__global__ void __launch_bounds__(256) prep_k(TJobs jobs, unsigned* poolk)
{
    __shared__ float tbuf[32][33];
    int b = blockIdx.x;
    if (b == 0) {
        for (int idx = threadIdx.x; idx < BATCH * DIM; idx += 256) poolk[idx] = 0u;
    }
    int k = 0;
#pragma unroll
    for (int t = 1; t < 12; t++) if (jobs.j[t].base <= b) k = t;
    const TJ job = jobs.j[k];
    int t = b - job.base;
    int txt = (job.J + 31) / 32;
    int j0 = (t % txt) * 32, i0 = (t / txt) * 32;
    int tx = threadIdx.x & 31, ty = threadIdx.x >> 5;
    for (int yy = ty; yy < 32; yy += 8) {
        int i = i0 + yy, j = j0 + tx;
        tbuf[yy][tx] = (i < job.I && j < job.J) ? job.src[(long)i * job.J + j] : 0.f;
    }
    __syncthreads();
    for (int yy = ty; yy < 32; yy += 8) {
        int j = j0 + yy, i = i0 + tx;
        if (j < job.J && i < job.I)
            job.dst[((long)(j >> 2) * job.I + i) * 4 + (j & 3)] = tbuf[tx][yy];
    }
}

// ---------------- tropical GEMM core: TM=4, row-major A tile, j-packed weights ----
template<int NT, int J, bool PSTAGE>
__device__ __forceinline__ void core4(
    const float* __restrict__ Ab, const float4* __restrict__ W4,
    float* As, int I, int m0, int ic, float out[4])
{
    const int tid = threadIdx.x;
    if (PSTAGE) {
        for (int idx = tid; idx < 4 * J; idx += NT) {
            int r = idx / J, j = idx - r * J;
            int m = m0 + r;
            int bb = m / NPATCH, n = m - bb * NPATCH;
            int gy = n / GRIDW, gx = n - gy * GRIDW;
            As[r * J + j] = Ab[((long)bb * IMG + gy * PATCH + (j >> 4)) * IMG + gx * PATCH + (j & 15)];
        }
    } else {
        for (int idx = tid; idx < J; idx += NT) {   // J float4s = 4 rows * J/4
            int r = idx / (J / 4), jv = idx - r * (J / 4);
            ((float4*)As)[idx] = ((const float4*)(Ab + (long)(m0 + r) * J))[jv];
        }
    }
    __syncthreads();
    float c0[4], c1[4], c2[4], c3[4];
#pragma unroll
    for (int r = 0; r < 4; r++) { c0[r] = NEG_INF; c1[r] = NEG_INF; c2[r] = NEG_INF; c3[r] = NEG_INF; }
#pragma unroll 8
    for (int j = 0; j < J; j += 4) {
        float4 w = W4[(j >> 2) * I + ic];
        u64 w01 = pk2(w.x, w.y), w23 = pk2(w.z, w.w);
#pragma unroll
        for (int r = 0; r < 4; r++) {
            ulonglong2 a = *(const ulonglong2*)(As + r * J + j);
            u64 t0 = addx2(a.x, w01), t1 = addx2(a.y, w23);
            float x, y;
            upk2(t0, x, y); c0[r] = fmaxf(c0[r], x); c1[r] = fmaxf(c1[r], y);
            upk2(t1, x, y); c2[r] = fmaxf(c2[r], x); c3[r] = fmaxf(c3[r], y);
        }
    }
#pragma unroll
    for (int r = 0; r < 4; r++)
        out[r] = fmaxf(fmaxf(c0[r], c1[r]), fmaxf(c2[r], c3[r]));
}

// block-wide max of K values per thread (valid=false excludes this thread's values)
template<int NT, int K>
__device__ __forceinline__ void rowmaxK(float* red, const float* v, float* out, bool valid)
{
    const int NW = NT / 32;
    int lane = threadIdx.x & 31, wid = threadIdx.x >> 5;
    float x[K];
#pragma unroll
    for (int k = 0; k < K; k++) {
        x[k] = valid ? v[k] : NEG_INF;
#pragma unroll
        for (int o = 16; o > 0; o >>= 1) x[k] = fmaxf(x[k], __shfl_xor_sync(0xffffffffu, x[k], o));
    }
    __syncthreads();
    if (lane == 0) {
#pragma unroll
        for (int k = 0; k < K; k++) red[k * NW + wid] = x[k];
    }
    __syncthreads();
#pragma unroll
    for (int k = 0; k < K; k++) {
        float m = red[k * NW];
#pragma unroll
        for (int w = 1; w < NW; w++) m = fmaxf(m, red[k * NW + w]);
        out[k] = m;
    }
}

// ---------------- fused kernels ----------------

// embed: patchify -> trop_mm -> +pos -> pnorm ; writes h, xn
__global__ void __launch_bounds__(128) embed_k(
    const float* __restrict__ x, const float* __restrict__ wte4, const float* __restrict__ pos,
    float* __restrict__ h, float* __restrict__ xn)
{
    __shared__ __align__(16) float As[4 * PD];
    __shared__ float red[4 * 4];
    const int m0 = blockIdx.x * 4, i = threadIdx.x;
    float acc[4];
    core4<128, PD, true>(x, (const float4*)wte4, As, DIM, m0, i, acc);
    const int n0 = m0 - (m0 / NPATCH) * NPATCH;
#pragma unroll
    for (int r = 0; r < 4; r++) acc[r] += pos[(n0 + r) * DIM + i];
    float rm[4];
    rowmaxK<128, 4>(red, acc, rm, true);
#pragma unroll
    for (int r = 0; r < 4; r++) {
        long m = m0 + r;
        h[m * DIM + i] = acc[r];
        xn[m * DIM + i] = acc[r] - rm[r];
    }
}

// q/k/v fused: 384 threads, A tile staged once; y = tid>>7 selects q/k/v
__global__ void __launch_bounds__(384) qkv_k(
    const float* __restrict__ xn, const float* __restrict__ wq4, const float* __restrict__ wk4,
    const float* __restrict__ wv4, float* __restrict__ q, float* __restrict__ kt4, float* __restrict__ v4)
{
    __shared__ __align__(16) float As[4 * DIM];
    const int m0 = blockIdx.x * 4, tid = threadIdx.x;
    const int y = tid >> 7, c = tid & 127;
    const float* W = (y == 0) ? wq4 : (y == 1) ? wk4 : wv4;
    float acc[4];
    core4<384, DIM, false>(xn, (const float4*)W, As, DIM, m0, c, acc);
    const int b = m0 / NPATCH, n0 = m0 - b * NPATCH;
#pragma unroll
    for (int r = 0; r < 4; r++) {
        int m = m0 + r, n = n0 + r;
        if (y == 0)      q[(long)m * DIM + c] = acc[r];
        else if (y == 1) kt4[(long)b * DIM * NPATCH + ((c >> 2) * NPATCH + n) * 4 + (c & 3)] = acc[r];
        else             v4 [(long)b * NPATCH * DIM + ((n >> 2) * DIM + c) * 4 + (n & 3)] = acc[r];
    }
}

// fused scores+attn+residual+ff1+ff2+residual for 4 rows of one batch, 256 threads.
// Score row-max cancels exactly through the output pnorm (omitted).
// If poolk != null (final layer): skip global h/xn writes, contribute to pool keys.
__global__ void __launch_bounds__(256) saff_k(
    const float* __restrict__ q, const float* __restrict__ kt4, const float* __restrict__ v4,
    const float* __restrict__ w14, const float* __restrict__ w24, const float* __restrict__ tau,
    float* __restrict__ h, float* __restrict__ xn, unsigned* __restrict__ poolk)
{
    __shared__ __align__(16) float qs[4 * DIM];
    __shared__ __align__(16) float scs[NPATCH * 4];
    __shared__ __align__(16) float part[4 * DIM];
    __shared__ __align__(16) float xs[4 * DIM];
    __shared__ __align__(16) float hs[4 * DIM];
    __shared__ __align__(16) float fs[DFF * 4];
    __shared__ float red[8 * 8];
    const int b = blockIdx.y, m0 = blockIdx.x * 4;
    const int tid = threadIdx.x;
    const int d = tid & 127, hh = tid >> 7;
    const bool lo = (hh == 0);
    const long row0 = ((long)b * NPATCH + m0) * DIM;

    // ---- sa phase 1: raw scores for 4 rows (thread = key column n) ----
    {
        const int ic = min(tid, NPATCH - 1);
        float acc[4];
        core4<256, DIM, false>(q + (long)b * NPATCH * DIM,
                               (const float4*)(kt4 + (long)b * DIM * NPATCH),
                               qs, NPATCH, m0, ic, acc);
        if (tid < NPATCH) *(float4*)(scs + tid * 4) = make_float4(acc[0], acc[1], acc[2], acc[3]);
    }
    __syncthreads();

    // ---- sa phase 2: raw out[m,d] = max_n(sc[n,m] + v[n,d]); n-range split in halves ----
    {
        const int n0 = hh ? 96 : 0, n1 = hh ? 196 : 96;
        const float4* V4 = (const float4*)(v4 + (long)b * NPATCH * DIM);
        float pa[4], pb[4];
#pragma unroll
        for (int r = 0; r < 4; r++) { pa[r] = NEG_INF; pb[r] = NEG_INF; }
#pragma unroll 4
        for (int n = n0; n < n1; n += 4) {
            float4 vv = V4[(n >> 2) * DIM + d];
            float vs[4] = { vv.x, vv.y, vv.z, vv.w };
#pragma unroll
            for (int nn = 0; nn < 4; nn++) {
                u64 vd = pk2(vs[nn], vs[nn]);
                ulonglong2 s = *(const ulonglong2*)(scs + (n + nn) * 4);
                u64 t0 = addx2(s.x, vd), t1 = addx2(s.y, vd);
                float x, y;
                float* p = (nn & 1) ? pb : pa;
                upk2(t0, x, y); p[0] = fmaxf(p[0], x); p[1] = fmaxf(p[1], y);
                upk2(t1, x, y); p[2] = fmaxf(p[2], x); p[3] = fmaxf(p[3], y);
            }
        }
        float raw[4];
#pragma unroll
        for (int r = 0; r < 4; r++) raw[r] = fmaxf(pa[r], pb[r]);
        if (hh) *(float4*)(part + d * 4) = make_float4(raw[0], raw[1], raw[2], raw[3]);
        __syncthreads();

        // epilogue: combine halves + joint reduction; h/xn go to SMEM (hs/xs)
        float v8[8];
#pragma unroll
        for (int k = 0; k < 8; k++) v8[k] = NEG_INF;
        if (lo) {
            float4 o = *(const float4*)(part + d * 4);
            v8[0] = fmaxf(raw[0], o.x); v8[1] = fmaxf(raw[1], o.y);
            v8[2] = fmaxf(raw[2], o.z); v8[3] = fmaxf(raw[3], o.w);
#pragma unroll
            for (int r = 0; r < 4; r++) v8[4 + r] = h[row0 + r * DIM + d];
        }
        float o8[8];
        rowmaxK<256, 8>(red, v8, o8, lo);
        if (lo) {
#pragma unroll
            for (int r = 0; r < 4; r++) {
                float hv = fmaxf(v8[4 + r], v8[r] - o8[r]);
                float hm = fmaxf(o8[4 + r], 0.f);
                hs[r * DIM + d] = hv;
                xs[r * DIM + d] = hv - hm;
            }
        }
    }
    __syncthreads();

    // ---- ff phase 1: ffh (thread = DFF column), reading xs from SMEM ----
    {
        const float4* W1 = (const float4*)w14;
        float c0[4], c1[4], c2[4], c3[4];
#pragma unroll
        for (int r = 0; r < 4; r++) { c0[r] = NEG_INF; c1[r] = NEG_INF; c2[r] = NEG_INF; c3[r] = NEG_INF; }
#pragma unroll 8
        for (int j = 0; j < DIM; j += 4) {
            float4 w = W1[(j >> 2) * DFF + tid];
            u64 w01 = pk2(w.x, w.y), w23 = pk2(w.z, w.w);
#pragma unroll
            for (int r = 0; r < 4; r++) {
                ulonglong2 a = *(const ulonglong2*)(xs + r * DIM + j);
                u64 t0 = addx2(a.x, w01), t1 = addx2(a.y, w23);
                float x, y;
                upk2(t0, x, y); c0[r] = fmaxf(c0[r], x); c1[r] = fmaxf(c1[r], y);
                upk2(t1, x, y); c2[r] = fmaxf(c2[r], x); c3[r] = fmaxf(c3[r], y);
            }
        }
        float tv = tau[0];
        float o0 = fmaxf(fmaxf(fmaxf(c0[0], c1[0]), fmaxf(c2[0], c3[0])), tv);
        float o1 = fmaxf(fmaxf(fmaxf(c0[1], c1[1]), fmaxf(c2[1], c3[1])), tv);
        float o2 = fmaxf(fmaxf(fmaxf(c0[2], c1[2]), fmaxf(c2[2], c3[2])), tv);
        float o3 = fmaxf(fmaxf(fmaxf(c0[3], c1[3]), fmaxf(c2[3], c3[3])), tv);
        *(float4*)(fs + tid * 4) = make_float4(o0, o1, o2, o3);
    }
    __syncthreads();

    // ---- ff phase 2: raw ff[m,d] = max_j(fs[j,m] + w2[d,j]); j-range split in halves ----
    {
        const int j0 = hh * 128, j1 = j0 + 128;
        const float4* W2 = (const float4*)w24;
        float pa[4], pb[4];
#pragma unroll
        for (int r = 0; r < 4; r++) { pa[r] = NEG_INF; pb[r] = NEG_INF; }
#pragma unroll 4
        for (int j = j0; j < j1; j += 4) {
            float4 ww = W2[(j >> 2) * DIM + d];
            float ws[4] = { ww.x, ww.y, ww.z, ww.w };
#pragma unroll
            for (int jj = 0; jj < 4; jj++) {
                u64 wd = pk2(ws[jj], ws[jj]);
                ulonglong2 s = *(const ulonglong2*)(fs + (j + jj) * 4);
                u64 t0 = addx2(s.x, wd), t1 = addx2(s.y, wd);
                float x, y;
                float* p = (jj & 1) ? pb : pa;
                upk2(t0, x, y); p[0] = fmaxf(p[0], x); p[1] = fmaxf(p[1], y);
                upk2(t1, x, y); p[2] = fmaxf(p[2], x); p[3] = fmaxf(p[3], y);
            }
        }
        float raw[4];
#pragma unroll
        for (int r = 0; r < 4; r++) raw[r] = fmaxf(pa[r], pb[r]);
        __syncthreads();            // part reuse from sa phase
        if (hh) *(float4*)(part + d * 4) = make_float4(raw[0], raw[1], raw[2], raw[3]);
        __syncthreads();

        float v8[8];
#pragma unroll
        for (int k = 0; k < 8; k++) v8[k] = NEG_INF;
        if (lo) {
            float4 o = *(const float4*)(part + d * 4);
            v8[0] = fmaxf(raw[0], o.x); v8[1] = fmaxf(raw[1], o.y);
            v8[2] = fmaxf(raw[2], o.z); v8[3] = fmaxf(raw[3], o.w);
#pragma unroll
            for (int r = 0; r < 4; r++) v8[4 + r] = hs[r * DIM + d];
        }
        float o8[8];
        rowmaxK<256, 8>(red, v8, o8, lo);
        if (lo) {
            float hv[4];
#pragma unroll
            for (int r = 0; r < 4; r++)
                hv[r] = fmaxf(v8[4 + r], v8[r] - o8[r]);
            if (poolk == nullptr) {
#pragma unroll
                for (int r = 0; r < 4; r++) {
                    float hm = fmaxf(o8[4 + r], 0.f);
                    h[row0 + r * DIM + d] = hv[r];
                    xn[row0 + r * DIM + d] = hv[r] - hm;
                }
            } else {
                float pm = fmaxf(fmaxf(hv[0], hv[1]), fmaxf(hv[2], hv[3]));
                atomicMax(&poolk[b * DIM + d], fkey(pm));
            }
        }
    }
}

__global__ void __launch_bounds__(128) head_k(
    const unsigned* __restrict__ poolk, const float* __restrict__ w4,
    const float* __restrict__ ls, float* __restrict__ O)
{
    __shared__ float sp[DIM];
    int b = blockIdx.y, tid = threadIdx.x;
    sp[tid] = funkey(poolk[b * DIM + tid]);
    __syncthreads();
    int c = blockIdx.x * 128 + tid;
    if (c < NCLS) {
        const float4* W = (const float4*)w4;
        float acc = NEG_INF;
#pragma unroll 4
        for (int j = 0; j < DIM; j += 4) {
            float4 w = W[(j >> 2) * NCLS + c];
            acc = fmaxf(acc, sp[j + 0] + w.x);
            acc = fmaxf(acc, sp[j + 1] + w.y);
            acc = fmaxf(acc, sp[j + 2] + w.z);
            acc = fmaxf(acc, sp[j + 3] + w.w);
        }
        O[(long)b * NCLS + c] = acc * ls[0];
    }
}

// ---------------- launch ----------------
extern "C" void kernel_launch(void* const* d_in, const int* in_sizes, int n_in,
                              void* d_out, int out_size)
{
    (void)in_sizes; (void)n_in; (void)out_size;
    const float* x      = (const float*)d_in[0];
    const float* embedW = (const float*)d_in[1];
    const float* pos    = (const float*)d_in[2];
    const float* W[2][5];
    const float* tau[2];
    for (int l = 0; l < 2; l++) {
        int base = 3 + l * 6;
        for (int k = 0; k < 5; k++) W[l][k] = (const float*)d_in[base + k];
        tau[l] = (const float*)d_in[base + 5];
    }
    const float* headW  = (const float*)d_in[15];
    const float* lscale = (const float*)d_in[16];
    float* out = (float*)d_out;

    float *h, *xn, *q, *kt4, *v4;
    unsigned* poolk;
    float *wte4, *wtq4, *wtk4, *wtv4, *wt14, *wt24, *wth4;
    cudaGetSymbolAddress((void**)&h,    g_h);
    cudaGetSymbolAddress((void**)&xn,   g_xn);
    cudaGetSymbolAddress((void**)&q,    g_q);
    cudaGetSymbolAddress((void**)&kt4,  g_kt4);
    cudaGetSymbolAddress((void**)&v4,   g_v4);
    cudaGetSymbolAddress((void**)&poolk,g_poolk);
    cudaGetSymbolAddress((void**)&wte4, g_wte4);
    cudaGetSymbolAddress((void**)&wtq4, g_wtq4);
    cudaGetSymbolAddress((void**)&wtk4, g_wtk4);
    cudaGetSymbolAddress((void**)&wtv4, g_wtv4);
    cudaGetSymbolAddress((void**)&wt14, g_wt14);
    cudaGetSymbolAddress((void**)&wt24, g_wt24);
    cudaGetSymbolAddress((void**)&wth4, g_wth4);

    TJobs jobs;
    int base = 0, nj = 0;
    auto addJob = [&](const float* s, float* d, int I, int J) {
        jobs.j[nj].src = s; jobs.j[nj].dst = d; jobs.j[nj].I = I; jobs.j[nj].J = J;
        jobs.j[nj].base = base;
        base += ((J + 31) / 32) * ((I + 31) / 32);
        nj++;
    };
    addJob(embedW, wte4, DIM, PD);
    for (int l = 0; l < 2; l++) {
        addJob(W[l][0], wtq4 + l * DIM * DIM, DIM, DIM);
        addJob(W[l][1], wtk4 + l * DIM * DIM, DIM, DIM);
        addJob(W[l][2], wtv4 + l * DIM * DIM, DIM, DIM);
        addJob(W[l][3], wt14 + l * DFF * DIM, DFF, DIM);
        addJob(W[l][4], wt24 + l * DIM * DFF, DIM, DFF);
    }
    addJob(headW, wth4, NCLS, DIM);

    prep_k<<<base, 256>>>(jobs, poolk);
    embed_k<<<392, 128>>>(x, wte4, pos, h, xn);

    for (int l = 0; l < 2; l++) {
        qkv_k<<<392, 384>>>(xn, wtq4 + l * DIM * DIM, wtk4 + l * DIM * DIM,
                            wtv4 + l * DIM * DIM, q, kt4, v4);
        saff_k<<<dim3(49, 8), 256>>>(q, kt4, v4,
                                     wt14 + l * DFF * DIM, wt24 + l * DIM * DFF, tau[l],
                                     h, xn, (l == 1) ? poolk : nullptr);
    }

    head_k<<<dim3(8, 8), 128>>>(poolk, wth4, lscale, out);
}

// round 15
// speedup vs baseline: 1.3343x; 1.1180x over previous
#include <cuda_runtime.h>

// ---------------- dims ----------------
#define BATCH   8
#define IMG     224
#define PATCH   16
#define GRIDW   14
#define NPATCH  196
#define PD      256
#define DIM     128
#define DFF     256
#define NCLS    1000
#define MROWS   (BATCH*NPATCH)   // 1568
#define NEG_INF (-3.0e38f)

typedef unsigned long long u64;

// ---------------- packed f32x2 helpers ----------------
__device__ __forceinline__ u64 pk2(float lo, float hi) {
    u64 r;
    asm("mov.b64 %0,{%1,%2};" : "=l"(r) : "r"(__float_as_uint(lo)), "r"(__float_as_uint(hi)));
    return r;
}
__device__ __forceinline__ u64 addx2(u64 a, u64 b) {
    u64 r;
    asm("add.rn.f32x2 %0,%1,%2;" : "=l"(r) : "l"(a), "l"(b));
    return r;
}
__device__ __forceinline__ void upk2(u64 v, float& a, float& b) {
    unsigned x, y;
    asm("mov.b64 {%0,%1},%2;" : "=r"(x), "=r"(y) : "l"(v));
    a = __uint_as_float(x); b = __uint_as_float(y);
}

// order-preserving float<->uint key for atomicMax pooling
__device__ __forceinline__ unsigned fkey(float f) {
    unsigned u = __float_as_uint(f);
    return (u & 0x80000000u) ? ~u : (u | 0x80000000u);
}
__device__ __forceinline__ float funkey(unsigned u) {
    return (u & 0x80000000u) ? __uint_as_float(u & 0x7fffffffu) : __uint_as_float(~u);
}

// ---------------- persistent scratch ----------------
__device__ float    g_h   [MROWS*DIM];
__device__ float    g_xn  [MROWS*DIM];
__device__ float    g_q   [MROWS*DIM];
__device__ float    g_kt4 [BATCH*DIM*NPATCH];
__device__ float    g_v4  [BATCH*NPATCH*DIM];
__device__ unsigned g_poolk[BATCH*DIM];

// blocked weights: Wt4[((j>>2)*I + i)*4 + (j&3)] = W[i*J + j]
__device__ float g_wte4[PD*DIM];
__device__ float g_wtq4[2*DIM*DIM];
__device__ float g_wtk4[2*DIM*DIM];
__device__ float g_wtv4[2*DIM*DIM];
__device__ float g_wt14[2*DFF*DIM];
__device__ float g_wt24[2*DIM*DFF];
__device__ float g_wth4[NCLS*DIM];

// ---------------- prep: transpose+block ALL weights; clear pool keys ----------------
struct TJ { const float* src; float* dst; int I, J, base; };
struct TJobs { TJ j[12]; };

__global__ void __launch_bounds__(256) prep_k(TJobs jobs, unsigned* poolk)
{
    __shared__ float tbuf[32][33];
    int b = blockIdx.x;
    if (b == 0) {
        for (int idx = threadIdx.x; idx < BATCH * DIM; idx += 256) poolk[idx] = 0u;
    }
    int k = 0;
#pragma unroll
    for (int t = 1; t < 12; t++) if (jobs.j[t].base <= b) k = t;
    const TJ job = jobs.j[k];
    int t = b - job.base;
    int txt = (job.J + 31) / 32;
    int j0 = (t % txt) * 32, i0 = (t / txt) * 32;
    int tx = threadIdx.x & 31, ty = threadIdx.x >> 5;
    for (int yy = ty; yy < 32; yy += 8) {
        int i = i0 + yy, j = j0 + tx;
        tbuf[yy][tx] = (i < job.I && j < job.J) ? job.src[(long)i * job.J + j] : 0.f;
    }
    __syncthreads();
    for (int yy = ty; yy < 32; yy += 8) {
        int j = j0 + yy, i = i0 + tx;
        if (j < job.J && i < job.I)
            job.dst[((long)(j >> 2) * job.I + i) * 4 + (j & 3)] = tbuf[tx][yy];
    }
}

// one 4-j step of the row-major core: 4 rows, packed weights (no MOVs)
__device__ __forceinline__ void step4(const float* As, int J, u64 w01, u64 w23,
                                      float c0[4], float c1[4], float c2[4], float c3[4], int j)
{
#pragma unroll
    for (int r = 0; r < 4; r++) {
        ulonglong2 a = *(const ulonglong2*)(As + r * J + j);
        u64 t0 = addx2(a.x, w01), t1 = addx2(a.y, w23);
        float x, y;
        upk2(t0, x, y); c0[r] = fmaxf(c0[r], x); c1[r] = fmaxf(c1[r], y);
        upk2(t1, x, y); c2[r] = fmaxf(c2[r], x); c3[r] = fmaxf(c3[r], y);
    }
}

// ---------------- tropical GEMM core: TM=4, depth-4 LDG pipeline ----------------
// out[r] = max_j ( A[m0+r, j] + W[ic, j] ),  W blocked float4 over j (viewed as ulonglong2)
template<int NT, int J, bool PSTAGE>
__device__ __forceinline__ void core4(
    const float* __restrict__ Ab, const float4* __restrict__ W4,
    float* As, int I, int m0, int ic, float out[4])
{
    const int tid = threadIdx.x;
    if (PSTAGE) {
        for (int idx = tid; idx < 4 * J; idx += NT) {
            int r = idx / J, j = idx - r * J;
            int m = m0 + r;
            int bb = m / NPATCH, n = m - bb * NPATCH;
            int gy = n / GRIDW, gx = n - gy * GRIDW;
            As[r * J + j] = Ab[((long)bb * IMG + gy * PATCH + (j >> 4)) * IMG + gx * PATCH + (j & 15)];
        }
    } else {
        for (int idx = tid; idx < J; idx += NT) {   // J float4s = 4 rows * J/4
            int r = idx / (J / 4), jv = idx - r * (J / 4);
            ((float4*)As)[idx] = ((const float4*)(Ab + (long)(m0 + r) * J))[jv];
        }
    }
    __syncthreads();
    float c0[4], c1[4], c2[4], c3[4];
#pragma unroll
    for (int r = 0; r < 4; r++) { c0[r] = NEG_INF; c1[r] = NEG_INF; c2[r] = NEG_INF; c3[r] = NEG_INF; }

    const ulonglong2* Wu = (const ulonglong2*)W4;
    ulonglong2 w0 = Wu[0 * I + ic], w1 = Wu[1 * I + ic], w2 = Wu[2 * I + ic], w3 = Wu[3 * I + ic];
    constexpr int JG = J / 16;
#pragma unroll
    for (int g = 0; g < JG; g++) {
        const int jb = g * 16;
        const int pf = (g + 1 < JG) ? (g + 1) * 4 : g * 4;
        ulonglong2 n0 = Wu[(pf + 0) * I + ic];
        ulonglong2 n1 = Wu[(pf + 1) * I + ic];
        ulonglong2 n2 = Wu[(pf + 2) * I + ic];
        ulonglong2 n3 = Wu[(pf + 3) * I + ic];
        step4(As, J, w0.x, w0.y, c0, c1, c2, c3, jb + 0);
        step4(As, J, w1.x, w1.y, c0, c1, c2, c3, jb + 4);
        step4(As, J, w2.x, w2.y, c0, c1, c2, c3, jb + 8);
        step4(As, J, w3.x, w3.y, c0, c1, c2, c3, jb + 12);
        w0 = n0; w1 = n1; w2 = n2; w3 = n3;
    }
#pragma unroll
    for (int r = 0; r < 4; r++)
        out[r] = fmaxf(fmaxf(c0[r], c1[r]), fmaxf(c2[r], c3[r]));
}

// ---------------- column-core for phase-2 loops (G per-thread column, S packed rows) ----
__device__ __forceinline__ void colstep(const float* S, int step, float4 g, float pa[4], float pb[4])
{
    const int n = step * 4;
    float gs[4] = { g.x, g.y, g.z, g.w };
#pragma unroll
    for (int nn = 0; nn < 4; nn++) {
        u64 gd = pk2(gs[nn], gs[nn]);
        ulonglong2 s = *(const ulonglong2*)(S + (n + nn) * 4);
        u64 t0 = addx2(s.x, gd), t1 = addx2(s.y, gd);
        float x, y;
        float* p = (nn & 1) ? pb : pa;
        upk2(t0, x, y); p[0] = fmaxf(p[0], x); p[1] = fmaxf(p[1], y);
        upk2(t1, x, y); p[2] = fmaxf(p[2], x); p[3] = fmaxf(p[3], y);
    }
}

// out[r] = max over steps s in [S0, S0+NS) of max_{nn} ( S[(4s+nn)*4 + r] + G[s*DIM + d][nn] )
template<int S0, int NS>
__device__ __forceinline__ void colcore(
    const float* __restrict__ S, const float4* __restrict__ G, int d, float out[4])
{
    constexpr int SMAX = S0 + NS - 1;
    float pa[4], pb[4];
#pragma unroll
    for (int r = 0; r < 4; r++) { pa[r] = NEG_INF; pb[r] = NEG_INF; }
    float4 g0 = G[S0 * DIM + d];
    float4 g1 = G[((S0 + 1 <= SMAX) ? S0 + 1 : SMAX) * DIM + d];
    float4 g2 = G[((S0 + 2 <= SMAX) ? S0 + 2 : SMAX) * DIM + d];
    float4 g3 = G[((S0 + 3 <= SMAX) ? S0 + 3 : SMAX) * DIM + d];
    constexpr int NG = (NS + 3) / 4;
#pragma unroll
    for (int gi = 0; gi < NG; gi++) {
        const int sb = S0 + gi * 4;
        const int p0 = (sb + 4 <= SMAX) ? sb + 4 : SMAX;
        const int p1 = (sb + 5 <= SMAX) ? sb + 5 : SMAX;
        const int p2 = (sb + 6 <= SMAX) ? sb + 6 : SMAX;
        const int p3 = (sb + 7 <= SMAX) ? sb + 7 : SMAX;
        float4 n0 = G[p0 * DIM + d], n1 = G[p1 * DIM + d];
        float4 n2 = G[p2 * DIM + d], n3 = G[p3 * DIM + d];
        colstep(S, sb + 0, g0, pa, pb);
        if (sb + 1 <= SMAX) colstep(S, sb + 1, g1, pa, pb);
        if (sb + 2 <= SMAX) colstep(S, sb + 2, g2, pa, pb);
        if (sb + 3 <= SMAX) colstep(S, sb + 3, g3, pa, pb);
        g0 = n0; g1 = n1; g2 = n2; g3 = n3;
    }
#pragma unroll
    for (int r = 0; r < 4; r++) out[r] = fmaxf(pa[r], pb[r]);
}

// block-wide max of K values per thread (valid=false excludes this thread's values)
template<int NT, int K>
__device__ __forceinline__ void rowmaxK(float* red, const float* v, float* out, bool valid)
{
    const int NW = NT / 32;
    int lane = threadIdx.x & 31, wid = threadIdx.x >> 5;
    float x[K];
#pragma unroll
    for (int k = 0; k < K; k++) {
        x[k] = valid ? v[k] : NEG_INF;
#pragma unroll
        for (int o = 16; o > 0; o >>= 1) x[k] = fmaxf(x[k], __shfl_xor_sync(0xffffffffu, x[k], o));
    }
    __syncthreads();
    if (lane == 0) {
#pragma unroll
        for (int k = 0; k < K; k++) red[k * NW + wid] = x[k];
    }
    __syncthreads();
#pragma unroll
    for (int k = 0; k < K; k++) {
        float m = red[k * NW];
#pragma unroll
        for (int w = 1; w < NW; w++) m = fmaxf(m, red[k * NW + w]);
        out[k] = m;
    }
}

// ---------------- fused kernels ----------------

// embed: patchify -> trop_mm -> +pos -> pnorm ; writes h, xn
__global__ void __launch_bounds__(128, 4) embed_k(
    const float* __restrict__ x, const float* __restrict__ wte4, const float* __restrict__ pos,
    float* __restrict__ h, float* __restrict__ xn)
{
    __shared__ __align__(16) float As[4 * PD];
    __shared__ float red[4 * 4];
    const int m0 = blockIdx.x * 4, i = threadIdx.x;
    float acc[4];
    core4<128, PD, true>(x, (const float4*)wte4, As, DIM, m0, i, acc);
    const int n0 = m0 - (m0 / NPATCH) * NPATCH;
#pragma unroll
    for (int r = 0; r < 4; r++) acc[r] += pos[(n0 + r) * DIM + i];
    float rm[4];
    rowmaxK<128, 4>(red, acc, rm, true);
#pragma unroll
    for (int r = 0; r < 4; r++) {
        long m = m0 + r;
        h[m * DIM + i] = acc[r];
        xn[m * DIM + i] = acc[r] - rm[r];
    }
}

// q/k/v fused: 384 threads, A tile staged once; y = tid>>7 selects q/k/v
__global__ void __launch_bounds__(384, 2) qkv_k(
    const float* __restrict__ xn, const float* __restrict__ wq4, const float* __restrict__ wk4,
    const float* __restrict__ wv4, float* __restrict__ q, float* __restrict__ kt4, float* __restrict__ v4)
{
    __shared__ __align__(16) float As[4 * DIM];
    const int m0 = blockIdx.x * 4, tid = threadIdx.x;
    const int y = tid >> 7, c = tid & 127;
    const float* W = (y == 0) ? wq4 : (y == 1) ? wk4 : wv4;
    float acc[4];
    core4<384, DIM, false>(xn, (const float4*)W, As, DIM, m0, c, acc);
    const int b = m0 / NPATCH, n0 = m0 - b * NPATCH;
#pragma unroll
    for (int r = 0; r < 4; r++) {
        int m = m0 + r, n = n0 + r;
        if (y == 0)      q[(long)m * DIM + c] = acc[r];
        else if (y == 1) kt4[(long)b * DIM * NPATCH + ((c >> 2) * NPATCH + n) * 4 + (c & 3)] = acc[r];
        else             v4 [(long)b * NPATCH * DIM + ((n >> 2) * DIM + c) * 4 + (n & 3)] = acc[r];
    }
}

// fused scores+attn+residual+ff1+ff2+residual for 4 rows of one batch, 256 threads.
// Score row-max cancels exactly through the output pnorm (omitted).
// If poolk != null (final layer): skip global h/xn writes, contribute to pool keys.
__global__ void __launch_bounds__(256, 3) saff_k(
    const float* __restrict__ q, const float* __restrict__ kt4, const float* __restrict__ v4,
    const float* __restrict__ w14, const float* __restrict__ w24, const float* __restrict__ tau,
    float* __restrict__ h, float* __restrict__ xn, unsigned* __restrict__ poolk)
{
    __shared__ __align__(16) float qs[4 * DIM];
    __shared__ __align__(16) float scs[NPATCH * 4];
    __shared__ __align__(16) float part[4 * DIM];
    __shared__ __align__(16) float xs[4 * DIM];
    __shared__ __align__(16) float hs[4 * DIM];
    __shared__ __align__(16) float fs[DFF * 4];
    __shared__ float red[8 * 8];
    const int b = blockIdx.y, m0 = blockIdx.x * 4;
    const int tid = threadIdx.x;
    const int d = tid & 127, hh = tid >> 7;
    const bool lo = (hh == 0);
    const long row0 = ((long)b * NPATCH + m0) * DIM;

    // ---- sa phase 1: raw scores for 4 rows (thread = key column n) ----
    {
        const int ic = min(tid, NPATCH - 1);
        float acc[4];
        core4<256, DIM, false>(q + (long)b * NPATCH * DIM,
                               (const float4*)(kt4 + (long)b * DIM * NPATCH),
                               qs, NPATCH, m0, ic, acc);
        if (tid < NPATCH) *(float4*)(scs + tid * 4) = make_float4(acc[0], acc[1], acc[2], acc[3]);
    }
    __syncthreads();

    // ---- sa phase 2: raw out[m,d] = max_n(sc[n,m] + v[n,d]); n-range split in halves ----
    {
        const float4* V4 = (const float4*)(v4 + (long)b * NPATCH * DIM);
        float raw[4];
        if (lo) colcore<0, 24>(scs, V4, d, raw);     // n = 0..95
        else    colcore<24, 25>(scs, V4, d, raw);    // n = 96..195
        if (hh) *(float4*)(part + d * 4) = make_float4(raw[0], raw[1], raw[2], raw[3]);
        __syncthreads();

        // epilogue: combine halves + joint reduction; h/xn go to SMEM (hs/xs)
        float v8[8];
#pragma unroll
        for (int k = 0; k < 8; k++) v8[k] = NEG_INF;
        if (lo) {
            float4 o = *(const float4*)(part + d * 4);
            v8[0] = fmaxf(raw[0], o.x); v8[1] = fmaxf(raw[1], o.y);
            v8[2] = fmaxf(raw[2], o.z); v8[3] = fmaxf(raw[3], o.w);
#pragma unroll
            for (int r = 0; r < 4; r++) v8[4 + r] = h[row0 + r * DIM + d];
        }
        float o8[8];
        rowmaxK<256, 8>(red, v8, o8, lo);
        if (lo) {
#pragma unroll
            for (int r = 0; r < 4; r++) {
                float hv = fmaxf(v8[4 + r], v8[r] - o8[r]);
                float hm = fmaxf(o8[4 + r], 0.f);
                hs[r * DIM + d] = hv;
                xs[r * DIM + d] = hv - hm;
            }
        }
    }
    __syncthreads();

    // ---- ff phase 1: ffh (thread = DFF column), reading xs from SMEM ----
    {
        const ulonglong2* W1u = (const ulonglong2*)w14;
        float c0[4], c1[4], c2[4], c3[4];
#pragma unroll
        for (int r = 0; r < 4; r++) { c0[r] = NEG_INF; c1[r] = NEG_INF; c2[r] = NEG_INF; c3[r] = NEG_INF; }
        ulonglong2 w0 = W1u[0 * DFF + tid], w1 = W1u[1 * DFF + tid];
        ulonglong2 w2 = W1u[2 * DFF + tid], w3 = W1u[3 * DFF + tid];
#pragma unroll
        for (int g = 0; g < 8; g++) {
            const int jb = g * 16;
            const int pf = (g < 7) ? (g + 1) * 4 : g * 4;
            ulonglong2 n0 = W1u[(pf + 0) * DFF + tid];
            ulonglong2 n1 = W1u[(pf + 1) * DFF + tid];
            ulonglong2 n2 = W1u[(pf + 2) * DFF + tid];
            ulonglong2 n3 = W1u[(pf + 3) * DFF + tid];
            step4(xs, DIM, w0.x, w0.y, c0, c1, c2, c3, jb + 0);
            step4(xs, DIM, w1.x, w1.y, c0, c1, c2, c3, jb + 4);
            step4(xs, DIM, w2.x, w2.y, c0, c1, c2, c3, jb + 8);
            step4(xs, DIM, w3.x, w3.y, c0, c1, c2, c3, jb + 12);
            w0 = n0; w1 = n1; w2 = n2; w3 = n3;
        }
        float tv = tau[0];
        float o0 = fmaxf(fmaxf(fmaxf(c0[0], c1[0]), fmaxf(c2[0], c3[0])), tv);
        float o1 = fmaxf(fmaxf(fmaxf(c0[1], c1[1]), fmaxf(c2[1], c3[1])), tv);
        float o2 = fmaxf(fmaxf(fmaxf(c0[2], c1[2]), fmaxf(c2[2], c3[2])), tv);
        float o3 = fmaxf(fmaxf(fmaxf(c0[3], c1[3]), fmaxf(c2[3], c3[3])), tv);
        *(float4*)(fs + tid * 4) = make_float4(o0, o1, o2, o3);
    }
    __syncthreads();

    // ---- ff phase 2: raw ff[m,d] = max_j(fs[j,m] + w2[d,j]); j-range split in halves ----
    {
        const float4* W2 = (const float4*)w24;
        float raw[4];
        if (lo) colcore<0, 32>(fs, W2, d, raw);      // j = 0..127
        else    colcore<32, 32>(fs, W2, d, raw);     // j = 128..255
        __syncthreads();            // part reuse from sa phase
        if (hh) *(float4*)(part + d * 4) = make_float4(raw[0], raw[1], raw[2], raw[3]);
        __syncthreads();

        float v8[8];
#pragma unroll
        for (int k = 0; k < 8; k++) v8[k] = NEG_INF;
        if (lo) {
            float4 o = *(const float4*)(part + d * 4);
            v8[0] = fmaxf(raw[0], o.x); v8[1] = fmaxf(raw[1], o.y);
            v8[2] = fmaxf(raw[2], o.z); v8[3] = fmaxf(raw[3], o.w);
#pragma unroll
            for (int r = 0; r < 4; r++) v8[4 + r] = hs[r * DIM + d];
        }
        float o8[8];
        rowmaxK<256, 8>(red, v8, o8, lo);
        if (lo) {
            float hv[4];
#pragma unroll
            for (int r = 0; r < 4; r++)
                hv[r] = fmaxf(v8[4 + r], v8[r] - o8[r]);
            if (poolk == nullptr) {
#pragma unroll
                for (int r = 0; r < 4; r++) {
                    float hm = fmaxf(o8[4 + r], 0.f);
                    h[row0 + r * DIM + d] = hv[r];
                    xn[row0 + r * DIM + d] = hv[r] - hm;
                }
            } else {
                float pm = fmaxf(fmaxf(hv[0], hv[1]), fmaxf(hv[2], hv[3]));
                atomicMax(&poolk[b * DIM + d], fkey(pm));
            }
        }
    }
}

__global__ void __launch_bounds__(128) head_k(
    const unsigned* __restrict__ poolk, const float* __restrict__ w4,
    const float* __restrict__ ls, float* __restrict__ O)
{
    __shared__ float sp[DIM];
    int b = blockIdx.y, tid = threadIdx.x;
    sp[tid] = funkey(poolk[b * DIM + tid]);
    __syncthreads();
    int c = blockIdx.x * 128 + tid;
    if (c < NCLS) {
        const float4* W = (const float4*)w4;
        float acc = NEG_INF;
#pragma unroll 4
        for (int j = 0; j < DIM; j += 4) {
            float4 w = W[(j >> 2) * NCLS + c];
            acc = fmaxf(acc, sp[j + 0] + w.x);
            acc = fmaxf(acc, sp[j + 1] + w.y);
            acc = fmaxf(acc, sp[j + 2] + w.z);
            acc = fmaxf(acc, sp[j + 3] + w.w);
        }
        O[(long)b * NCLS + c] = acc * ls[0];
    }
}

// ---------------- launch ----------------
extern "C" void kernel_launch(void* const* d_in, const int* in_sizes, int n_in,
                              void* d_out, int out_size)
{
    (void)in_sizes; (void)n_in; (void)out_size;
    const float* x      = (const float*)d_in[0];
    const float* embedW = (const float*)d_in[1];
    const float* pos    = (const float*)d_in[2];
    const float* W[2][5];
    const float* tau[2];
    for (int l = 0; l < 2; l++) {
        int base = 3 + l * 6;
        for (int k = 0; k < 5; k++) W[l][k] = (const float*)d_in[base + k];
        tau[l] = (const float*)d_in[base + 5];
    }
    const float* headW  = (const float*)d_in[15];
    const float* lscale = (const float*)d_in[16];
    float* out = (float*)d_out;

    float *h, *xn, *q, *kt4, *v4;
    unsigned* poolk;
    float *wte4, *wtq4, *wtk4, *wtv4, *wt14, *wt24, *wth4;
    cudaGetSymbolAddress((void**)&h,    g_h);
    cudaGetSymbolAddress((void**)&xn,   g_xn);
    cudaGetSymbolAddress((void**)&q,    g_q);
    cudaGetSymbolAddress((void**)&kt4,  g_kt4);
    cudaGetSymbolAddress((void**)&v4,   g_v4);
    cudaGetSymbolAddress((void**)&poolk,g_poolk);
    cudaGetSymbolAddress((void**)&wte4, g_wte4);
    cudaGetSymbolAddress((void**)&wtq4, g_wtq4);
    cudaGetSymbolAddress((void**)&wtk4, g_wtk4);
    cudaGetSymbolAddress((void**)&wtv4, g_wtv4);
    cudaGetSymbolAddress((void**)&wt14, g_wt14);
    cudaGetSymbolAddress((void**)&wt24, g_wt24);
    cudaGetSymbolAddress((void**)&wth4, g_wth4);

    TJobs jobs;
    int base = 0, nj = 0;
    auto addJob = [&](const float* s, float* d, int I, int J) {
        jobs.j[nj].src = s; jobs.j[nj].dst = d; jobs.j[nj].I = I; jobs.j[nj].J = J;
        jobs.j[nj].base = base;
        base += ((J + 31) / 32) * ((I + 31) / 32);
        nj++;
    };
    addJob(embedW, wte4, DIM, PD);
    for (int l = 0; l < 2; l++) {
        addJob(W[l][0], wtq4 + l * DIM * DIM, DIM, DIM);
        addJob(W[l][1], wtk4 + l * DIM * DIM, DIM, DIM);
        addJob(W[l][2], wtv4 + l * DIM * DIM, DIM, DIM);
        addJob(W[l][3], wt14 + l * DFF * DIM, DFF, DIM);
        addJob(W[l][4], wt24 + l * DIM * DFF, DIM, DFF);
    }
    addJob(headW, wth4, NCLS, DIM);

    prep_k<<<base, 256>>>(jobs, poolk);
    embed_k<<<392, 128>>>(x, wte4, pos, h, xn);

    for (int l = 0; l < 2; l++) {
        qkv_k<<<392, 384>>>(xn, wtq4 + l * DIM * DIM, wtk4 + l * DIM * DIM,
                            wtv4 + l * DIM * DIM, q, kt4, v4);
        saff_k<<<dim3(49, 8), 256>>>(q, kt4, v4,
                                     wt14 + l * DFF * DIM, wt24 + l * DIM * DFF, tau[l],
                                     h, xn, (l == 1) ? poolk : nullptr);
    }

    head_k<<<dim3(8, 8), 128>>>(poolk, wth4, lscale, out);
}